// round 6
// baseline (speedup 1.0000x reference)
#include <cuda_runtime.h>
#include <cuda_bf16.h>
#include <mma.h>
#include <math.h>
#include <cstdint>

using namespace nvcuda;

// ---------------- constants for this problem ----------------
#define Hdim   1024
#define STATE  16
#define INNER  2048           // H * 2
#define DTRANK 64             // H / 16
#define KCONV  4
#define Bb     2
#define Ll     2048
#define BT     (Bb * Ll)      // 4096 rows
#define XZ_N   (2 * INNER)    // 4096
#define XDBL_N 96             // DT_RANK + 2*STATE
#define NSPLIT 8

// ---------------- scratch (static device globals; no runtime alloc) -----
__device__ float g_xz  [(size_t)BT * XZ_N];    // xz = x @ W_in^T      (64MB)
__device__ float g_xin [(size_t)BT * INNER];   // post conv+silu       (32MB)
__device__ float g_xdbl[(size_t)BT * XDBL_N];  // x_dbl                (1.5MB)
__device__ float g_dt  [(size_t)BT * INNER];   // dt (pre then post)   (32MB)
__device__ float g_gate[(size_t)BT * INNER];   // gated y              (32MB)
__device__ float g_part[(size_t)NSPLIT * BT * XDBL_N]; // split-K partials

// ---------------- helpers ----------------
__device__ __forceinline__ float ex2f(float x) {
    float y; asm("ex2.approx.ftz.f32 %0, %1;" : "=f"(y) : "f"(x)); return y;
}
#define LOG2E 1.4426950408889634f

__device__ __forceinline__ void cp_async16(void* smem, const void* gmem, int pbytes) {
    unsigned int s = (unsigned int)__cvta_generic_to_shared(smem);
    asm volatile("cp.async.cg.shared.global [%0], [%1], 16, %2;\n"
                 :: "r"(s), "l"(gmem), "r"(pbytes));
}
__device__ __forceinline__ void cp_commit() {
    asm volatile("cp.async.commit_group;\n");
}

// ---------------- pipelined tf32 WMMA NT GEMM ----------------------------
// C[M,N] = A[M,K] * B[N,K]^T.  128x128 tile, BK=16, 2-stage cp.async.
// 256 threads (8 warps, each 32x64). Optional split-K over blockIdx.z.
// Requirements: M%128==0, N%16==0, chunk%16==0, rows 16B-aligned.
__global__ __launch_bounds__(256, 2)
void wmma_tf32_nt(const float* __restrict__ A, int lda,
                  const float* __restrict__ B, int ldb,
                  float* __restrict__ C, int ldc,
                  int M, int N, int Ktot, int nsplit)
{
    const int BM = 128, BN = 128, BK = 16;
    const int SA = 20, SB = 20;                 // padded smem strides (floats)
    __shared__ __align__(16) float As[2][BM * SA];
    __shared__ __align__(16) float Bs[2][BN * SB];

    int tid = threadIdx.x;
    int bm  = blockIdx.y * BM;
    int bn  = blockIdx.x * BN;

    int chunk = Ktot / nsplit;
    int kFrom = blockIdx.z * chunk;
    int nIter = chunk / BK;
    C += (size_t)blockIdx.z * M * ldc;

    int wid = tid >> 5;
    int row0 = (wid & 3) * 32;
    int col0 = (wid >> 2) * 64;

    // per-thread load slots: 2 float4 per matrix per stage
    int r0 = (tid * 2)     >> 2;  int kq0 = ((tid * 2)     & 3) * 4;
    int r1 = (tid * 2 + 1) >> 2;  int kq1 = ((tid * 2 + 1) & 3) * 4;
    // A rows always in-bounds (M multiple of 128); B rows may be OOB (N=96)
    int brow0 = bn + r0 < N ? bn + r0 : 0;  int bp0 = bn + r0 < N ? 16 : 0;
    int brow1 = bn + r1 < N ? bn + r1 : 0;  int bp1 = bn + r1 < N ? 16 : 0;

    wmma::fragment<wmma::accumulator, 16, 16, 8, float> acc[2][4];
    #pragma unroll
    for (int i = 0; i < 2; i++)
        #pragma unroll
        for (int j = 0; j < 4; j++) wmma::fill_fragment(acc[i][j], 0.0f);

    // ---- prefetch stage 0 ----
    {
        int k0 = kFrom;
        cp_async16(&As[0][r0 * SA + kq0], &A[(size_t)(bm + r0) * lda + k0 + kq0], 16);
        cp_async16(&As[0][r1 * SA + kq1], &A[(size_t)(bm + r1) * lda + k0 + kq1], 16);
        cp_async16(&Bs[0][r0 * SB + kq0], &B[(size_t)brow0 * ldb + k0 + kq0], bp0);
        cp_async16(&Bs[0][r1 * SB + kq1], &B[(size_t)brow1 * ldb + k0 + kq1], bp1);
        cp_commit();
    }

    for (int it = 0; it < nIter; it++) {
        int cur = it & 1;
        if (it + 1 < nIter) {
            int nxt = cur ^ 1;
            int k0 = kFrom + (it + 1) * BK;
            cp_async16(&As[nxt][r0 * SA + kq0], &A[(size_t)(bm + r0) * lda + k0 + kq0], 16);
            cp_async16(&As[nxt][r1 * SA + kq1], &A[(size_t)(bm + r1) * lda + k0 + kq1], 16);
            cp_async16(&Bs[nxt][r0 * SB + kq0], &B[(size_t)brow0 * ldb + k0 + kq0], bp0);
            cp_async16(&Bs[nxt][r1 * SB + kq1], &B[(size_t)brow1 * ldb + k0 + kq1], bp1);
            cp_commit();
            asm volatile("cp.async.wait_group 1;\n");
        } else {
            asm volatile("cp.async.wait_group 0;\n");
        }
        __syncthreads();

        #pragma unroll
        for (int kk = 0; kk < BK; kk += 8) {
            wmma::fragment<wmma::matrix_a, 16, 16, 8, wmma::precision::tf32, wmma::row_major> a[2];
            wmma::fragment<wmma::matrix_b, 16, 16, 8, wmma::precision::tf32, wmma::col_major> b[4];
            #pragma unroll
            for (int i = 0; i < 2; i++) {
                wmma::load_matrix_sync(a[i], &As[cur][(row0 + 16 * i) * SA + kk], SA);
                #pragma unroll
                for (int t = 0; t < a[i].num_elements; t++)
                    a[i].x[t] = wmma::__float_to_tf32(a[i].x[t]);
            }
            #pragma unroll
            for (int j = 0; j < 4; j++) {
                wmma::load_matrix_sync(b[j], &Bs[cur][(col0 + 16 * j) * SB + kk], SB);
                #pragma unroll
                for (int t = 0; t < b[j].num_elements; t++)
                    b[j].x[t] = wmma::__float_to_tf32(b[j].x[t]);
            }
            #pragma unroll
            for (int i = 0; i < 2; i++)
                #pragma unroll
                for (int j = 0; j < 4; j++)
                    wmma::mma_sync(acc[i][j], a[i], b[j], acc[i][j]);
        }
        __syncthreads();
    }

    #pragma unroll
    for (int i = 0; i < 2; i++) {
        int gr0 = bm + row0 + 16 * i;
        #pragma unroll
        for (int j = 0; j < 4; j++) {
            int gc0 = bn + col0 + 16 * j;
            if (gc0 < N)
                wmma::store_matrix_sync(&C[(size_t)gr0 * ldc + gc0], acc[i][j],
                                        ldc, wmma::mem_row_major);
        }
    }
}

// ---------------- split-K reduce for x_dbl -------------------------------
__global__ void splitk_reduce_kernel()
{
    int idx = blockIdx.x * blockDim.x + threadIdx.x;
    const int n = BT * XDBL_N;
    if (idx >= n) return;
    float s = 0.0f;
    #pragma unroll
    for (int z = 0; z < NSPLIT; z++)
        s += g_part[(size_t)z * n + idx];
    g_xdbl[idx] = s;
}

// ---------------- depthwise causal conv (k=4) + bias + silu --------------
__global__ void conv_silu_kernel(const float* __restrict__ conv_w,
                                 const float* __restrict__ conv_b)
{
    int idx = blockIdx.x * blockDim.x + threadIdx.x;   // over BT*INNER
    if (idx >= BT * INNER) return;
    int i  = idx & (INNER - 1);
    int bt = idx >> 11;
    int t  = bt & (Ll - 1);
    int b  = bt >> 11;

    float w0 = conv_w[i * KCONV + 0];
    float w1 = conv_w[i * KCONV + 1];
    float w2 = conv_w[i * KCONV + 2];
    float w3 = conv_w[i * KCONV + 3];

    const float* src = g_xz + (size_t)(b * Ll) * XZ_N + i;
    float acc = conv_b[i];
    if (t >= 3) acc = fmaf(w0, src[(size_t)(t - 3) * XZ_N], acc);
    if (t >= 2) acc = fmaf(w1, src[(size_t)(t - 2) * XZ_N], acc);
    if (t >= 1) acc = fmaf(w2, src[(size_t)(t - 1) * XZ_N], acc);
    acc = fmaf(w3, src[(size_t)t * XZ_N], acc);

    float s = 1.0f / (1.0f + ex2f(-acc * LOG2E));
    g_xin[(size_t)bt * INNER + i] = acc * s;
}

// ---------------- dt = softplus(dt_pre + b_dt) ---------------------------
__global__ void dt_softplus_kernel(const float* __restrict__ b_dt)
{
    int idx = blockIdx.x * blockDim.x + threadIdx.x;
    if (idx >= BT * INNER) return;
    int i = idx & (INNER - 1);
    float v = g_dt[idx] + b_dt[i];
    float r;
    if (v > 20.0f)      r = v;
    else if (v < -20.0f) r = expf(v);
    else                r = log1pf(expf(v));
    g_dt[idx] = r;
}

// ---------------- selective scan + fused gate ----------------------------
// lane-per-state; lane s==0 also applies (y + x*D) * silu(z) and stores.
__global__ __launch_bounds__(128)
void scan_kernel(const float* __restrict__ state0,
                 const float* __restrict__ A_log,
                 const float* __restrict__ Dp,
                 float* __restrict__ state_out)   // may be null
{
    int chan_base = blockIdx.x * 8;
    int ch = threadIdx.x >> 4;
    int s  = threadIdx.x & 15;
    int gchan = chan_base + ch;
    int b = gchan >> 11;
    int i = gchan & (INNER - 1);

    float a2 = -expf(A_log[(size_t)i * STATE + s]) * LOG2E;
    float Dv = Dp[i];
    float st = state0[((size_t)(b * INNER) + i) * STATE + s];

    const float* pdt = g_dt  + (size_t)(b * Ll) * INNER + i;
    const float* px  = g_xin + (size_t)(b * Ll) * INNER + i;
    const float* pB  = g_xdbl + (size_t)(b * Ll) * XDBL_N + DTRANK + s;
    const float* pC  = pB + STATE;
    const float* pz  = g_xz + (size_t)(b * Ll) * XZ_N + INNER + i;
    float*       py  = g_gate + (size_t)(b * Ll) * INNER + i;

    // software pipeline: preload t=0
    float dt = __ldg(pdt), x = __ldg(px), Bv = __ldg(pB), Cv = __ldg(pC);
    float z  = (s == 0) ? __ldg(pz) : 0.0f;

    for (int t = 0; t < Ll; t++) {
        pdt += INNER; px += INNER; pB += XDBL_N; pC += XDBL_N; pz += XZ_N;
        float ndt = 0.f, nx = 0.f, nB = 0.f, nC = 0.f, nz = 0.f;
        if (t + 1 < Ll) {
            ndt = __ldg(pdt); nx = __ldg(px);
            nB  = __ldg(pB);  nC = __ldg(pC);
            if (s == 0) nz = __ldg(pz);
        }

        float dA = ex2f(dt * a2);
        st = fmaf(dA, st, (dt * x) * Bv);
        float part = st * Cv;
        part += __shfl_xor_sync(0xffffffffu, part, 1);
        part += __shfl_xor_sync(0xffffffffu, part, 2);
        part += __shfl_xor_sync(0xffffffffu, part, 4);
        part += __shfl_xor_sync(0xffffffffu, part, 8);
        if (s == 0) {
            float sz = z / (1.0f + ex2f(-z * LOG2E));
            *py = (part + x * Dv) * sz;
        }
        py += INNER;
        dt = ndt; x = nx; Bv = nB; Cv = nC; z = nz;
    }

    if (state_out)
        state_out[((size_t)(b * INNER) + i) * STATE + s] = st;
}

// ---------------- launch ----------------
extern "C" void kernel_launch(void* const* d_in, const int* in_sizes, int n_in,
                              void* d_out, int out_size)
{
    const float* x      = (const float*)d_in[0];
    const float* state0 = (const float*)d_in[1];
    const float* W_in   = (const float*)d_in[2];
    const float* conv_w = (const float*)d_in[3];
    const float* conv_b = (const float*)d_in[4];
    const float* W_x    = (const float*)d_in[5];
    const float* W_dt   = (const float*)d_in[6];
    const float* b_dt   = (const float*)d_in[7];
    const float* A_log  = (const float*)d_in[8];
    const float* D      = (const float*)d_in[9];
    const float* W_out  = (const float*)d_in[10];

    float* out = (float*)d_out;
    const int out_main = BT * Hdim;
    const int state_elems = Bb * INNER * STATE;
    float* state_out = (out_size >= out_main + state_elems)
                         ? out + out_main : nullptr;

    float* xz   = nullptr; cudaGetSymbolAddress((void**)&xz,   g_xz);
    float* xin  = nullptr; cudaGetSymbolAddress((void**)&xin,  g_xin);
    float* xdbl = nullptr; cudaGetSymbolAddress((void**)&xdbl, g_xdbl);
    float* dtb  = nullptr; cudaGetSymbolAddress((void**)&dtb,  g_dt);
    float* gate = nullptr; cudaGetSymbolAddress((void**)&gate, g_gate);
    float* part = nullptr; cudaGetSymbolAddress((void**)&part, g_part);

    // 1) xz = x @ W_in^T : M=4096, N=4096, K=1024
    wmma_tf32_nt<<<dim3(XZ_N / 128, BT / 128, 1), 256>>>(
        x, Hdim, W_in, Hdim, xz, XZ_N, BT, XZ_N, Hdim, 1);

    // 2) depthwise conv + bias + silu -> g_xin
    {
        int n = BT * INNER;
        conv_silu_kernel<<<(n + 255) / 256, 256>>>(conv_w, conv_b);
    }

    // 3) x_dbl = xin @ W_x^T : M=4096, N=96, K=2048, split-K=8
    wmma_tf32_nt<<<dim3(1, BT / 128, NSPLIT), 256>>>(
        xin, INNER, W_x, INNER, part, XDBL_N, BT, XDBL_N, INNER, NSPLIT);
    {
        int n = BT * XDBL_N;
        splitk_reduce_kernel<<<(n + 255) / 256, 256>>>();
    }

    // 4) dt_pre = x_dbl[:, :64] @ W_dt^T : M=4096, N=2048, K=64
    wmma_tf32_nt<<<dim3(INNER / 128, BT / 128, 1), 256>>>(
        xdbl, XDBL_N, W_dt, DTRANK, dtb, INNER, BT, INNER, DTRANK, 1);

    // 5) dt = softplus(dt_pre + b_dt)
    {
        int n = BT * INNER;
        dt_softplus_kernel<<<(n + 255) / 256, 256>>>(b_dt);
    }

    // 6) selective scan with fused gating
    scan_kernel<<<(Bb * INNER) / 8, 128>>>(state0, A_log, D, state_out);

    // 7) out = gated @ W_out^T : M=4096, N=1024, K=2048
    wmma_tf32_nt<<<dim3(Hdim / 128, BT / 128, 1), 256>>>(
        gate, INNER, W_out, INNER, out, Hdim, BT, Hdim, INNER, 1);
}

// round 8
// speedup vs baseline: 1.0084x; 1.0084x over previous
#include <cuda_runtime.h>
#include <cuda_bf16.h>
#include <mma.h>
#include <math.h>
#include <cstdint>

using namespace nvcuda;

// ---------------- constants for this problem ----------------
#define Hdim   1024
#define STATE  16
#define INNER  2048           // H * 2
#define DTRANK 64             // H / 16
#define KCONV  4
#define Bb     2
#define Ll     2048
#define BT     (Bb * Ll)      // 4096 rows
#define XZ_N   (2 * INNER)    // 4096
#define XDBL_N 96             // DT_RANK + 2*STATE
#define NSPLIT 8

// ---------------- scratch (static device globals; no runtime alloc) -----
__device__ float g_xz  [(size_t)BT * XZ_N];    // xz = x @ W_in^T      (64MB)
__device__ float g_xin [(size_t)BT * INNER];   // post conv+silu       (32MB)
__device__ float g_xdbl[(size_t)BT * XDBL_N];  // x_dbl                (1.5MB)
__device__ float g_dt  [(size_t)BT * INNER];   // dt (pre then post)   (32MB)
__device__ float g_gate[(size_t)BT * INNER];   // gated y              (32MB)
__device__ float g_part[(size_t)NSPLIT * BT * XDBL_N]; // split-K partials

// ---------------- helpers ----------------
__device__ __forceinline__ float ex2f(float x) {
    float y; asm("ex2.approx.ftz.f32 %0, %1;" : "=f"(y) : "f"(x)); return y;
}
#define LOG2E 1.4426950408889634f

__device__ __forceinline__ float to_tf32(float x) {
    float r; asm("cvt.rna.tf32.f32 %0, %1;" : "=f"(r) : "f"(x)); return r;
}
__device__ __forceinline__ float4 to_tf32_v4(float4 v) {
    v.x = to_tf32(v.x); v.y = to_tf32(v.y);
    v.z = to_tf32(v.z); v.w = to_tf32(v.w);
    return v;
}

// ---------------- tf32 WMMA NT GEMM, register-prefetch pipelined ---------
// C[M,N] = A[M,K] * B[N,K]^T.  128x128 block tile, BK=16, 256 threads
// (8 warps, 32x64 each). tf32 rounding done ONCE at smem-store time.
// Next tile's LDGs issue before compute; STS at top of next iteration.
// Optional split-K over blockIdx.z. Reqs: M%128==0, chunk%16==0.
__global__ __launch_bounds__(256, 2)
void wmma_tf32_nt(const float* __restrict__ A, int lda,
                  const float* __restrict__ B, int ldb,
                  float* __restrict__ C, int ldc,
                  int M, int N, int Ktot, int nsplit)
{
    const int BM = 128, BN = 128, BK = 16;
    const int SA = 20, SB = 20;                 // padded smem strides (floats)
    __shared__ __align__(16) float As[BM * SA];
    __shared__ __align__(16) float Bs[BN * SB];

    int tid = threadIdx.x;
    int bm  = blockIdx.y * BM;
    int bn  = blockIdx.x * BN;

    int chunk = Ktot / nsplit;
    int kFrom = blockIdx.z * chunk;
    int nIter = chunk / BK;
    C += (size_t)blockIdx.z * M * ldc;

    int wid  = tid >> 5;
    int row0 = (wid & 3) * 32;
    int col0 = (wid >> 2) * 64;

    // per-thread load slots: 2 float4 from A, 2 from B per tile
    int r0 = (tid * 2)     >> 2;  int kq0 = ((tid * 2)     & 3) * 4;
    int r1 = (tid * 2 + 1) >> 2;  int kq1 = ((tid * 2 + 1) & 3) * 4;
    bool bok0 = (bn + r0) < N;
    bool bok1 = (bn + r1) < N;
    int  brow0 = bok0 ? bn + r0 : 0;
    int  brow1 = bok1 ? bn + r1 : 0;

    wmma::fragment<wmma::accumulator, 16, 16, 8, float> acc[2][4];
    #pragma unroll
    for (int i = 0; i < 2; i++)
        #pragma unroll
        for (int j = 0; j < 4; j++) wmma::fill_fragment(acc[i][j], 0.0f);

    // preload tile 0 into registers
    float4 va0, va1, vb0, vb1;
    {
        int k0 = kFrom;
        va0 = *reinterpret_cast<const float4*>(&A[(size_t)(bm + r0) * lda + k0 + kq0]);
        va1 = *reinterpret_cast<const float4*>(&A[(size_t)(bm + r1) * lda + k0 + kq1]);
        vb0 = bok0 ? *reinterpret_cast<const float4*>(&B[(size_t)brow0 * ldb + k0 + kq0])
                   : make_float4(0.f, 0.f, 0.f, 0.f);
        vb1 = bok1 ? *reinterpret_cast<const float4*>(&B[(size_t)brow1 * ldb + k0 + kq1])
                   : make_float4(0.f, 0.f, 0.f, 0.f);
    }

    for (int it = 0; it < nIter; it++) {
        // store current regs to smem (tf32-rounded once here)
        *reinterpret_cast<float4*>(&As[r0 * SA + kq0]) = to_tf32_v4(va0);
        *reinterpret_cast<float4*>(&As[r1 * SA + kq1]) = to_tf32_v4(va1);
        *reinterpret_cast<float4*>(&Bs[r0 * SB + kq0]) = to_tf32_v4(vb0);
        *reinterpret_cast<float4*>(&Bs[r1 * SB + kq1]) = to_tf32_v4(vb1);
        __syncthreads();

        // issue next tile's LDGs; latency overlaps with compute below
        if (it + 1 < nIter) {
            int k0 = kFrom + (it + 1) * BK;
            va0 = *reinterpret_cast<const float4*>(&A[(size_t)(bm + r0) * lda + k0 + kq0]);
            va1 = *reinterpret_cast<const float4*>(&A[(size_t)(bm + r1) * lda + k0 + kq1]);
            if (bok0) vb0 = *reinterpret_cast<const float4*>(&B[(size_t)brow0 * ldb + k0 + kq0]);
            if (bok1) vb1 = *reinterpret_cast<const float4*>(&B[(size_t)brow1 * ldb + k0 + kq1]);
        }

        #pragma unroll
        for (int kk = 0; kk < BK; kk += 8) {
            wmma::fragment<wmma::matrix_a, 16, 16, 8, wmma::precision::tf32, wmma::row_major> a[2];
            wmma::fragment<wmma::matrix_b, 16, 16, 8, wmma::precision::tf32, wmma::col_major> b[4];
            #pragma unroll
            for (int i = 0; i < 2; i++)
                wmma::load_matrix_sync(a[i], &As[(row0 + 16 * i) * SA + kk], SA);
            #pragma unroll
            for (int j = 0; j < 4; j++)
                wmma::load_matrix_sync(b[j], &Bs[(col0 + 16 * j) * SB + kk], SB);
            #pragma unroll
            for (int i = 0; i < 2; i++)
                #pragma unroll
                for (int j = 0; j < 4; j++)
                    wmma::mma_sync(acc[i][j], a[i], b[j], acc[i][j]);
        }
        __syncthreads();
    }

    #pragma unroll
    for (int i = 0; i < 2; i++) {
        int gr0 = bm + row0 + 16 * i;
        #pragma unroll
        for (int j = 0; j < 4; j++) {
            int gc0 = bn + col0 + 16 * j;
            if (gc0 < N)
                wmma::store_matrix_sync(&C[(size_t)gr0 * ldc + gc0], acc[i][j],
                                        ldc, wmma::mem_row_major);
        }
    }
}

// ---------------- split-K reduce for x_dbl -------------------------------
__global__ void splitk_reduce_kernel()
{
    int idx = blockIdx.x * blockDim.x + threadIdx.x;
    const int n = BT * XDBL_N;
    if (idx >= n) return;
    float s = 0.0f;
    #pragma unroll
    for (int z = 0; z < NSPLIT; z++)
        s += g_part[(size_t)z * n + idx];
    g_xdbl[idx] = s;
}

// ---------------- depthwise causal conv (k=4) + bias + silu --------------
__global__ void conv_silu_kernel(const float* __restrict__ conv_w,
                                 const float* __restrict__ conv_b)
{
    int idx = blockIdx.x * blockDim.x + threadIdx.x;   // over BT*INNER
    if (idx >= BT * INNER) return;
    int i  = idx & (INNER - 1);
    int bt = idx >> 11;
    int t  = bt & (Ll - 1);
    int b  = bt >> 11;

    float w0 = conv_w[i * KCONV + 0];
    float w1 = conv_w[i * KCONV + 1];
    float w2 = conv_w[i * KCONV + 2];
    float w3 = conv_w[i * KCONV + 3];

    const float* src = g_xz + (size_t)(b * Ll) * XZ_N + i;
    float acc = conv_b[i];
    if (t >= 3) acc = fmaf(w0, src[(size_t)(t - 3) * XZ_N], acc);
    if (t >= 2) acc = fmaf(w1, src[(size_t)(t - 2) * XZ_N], acc);
    if (t >= 1) acc = fmaf(w2, src[(size_t)(t - 1) * XZ_N], acc);
    acc = fmaf(w3, src[(size_t)t * XZ_N], acc);

    float s = 1.0f / (1.0f + ex2f(-acc * LOG2E));
    g_xin[(size_t)bt * INNER + i] = acc * s;
}

// ---------------- dt = softplus(dt_pre + b_dt) ---------------------------
__global__ void dt_softplus_kernel(const float* __restrict__ b_dt)
{
    int idx = blockIdx.x * blockDim.x + threadIdx.x;
    if (idx >= BT * INNER) return;
    int i = idx & (INNER - 1);
    float v = g_dt[idx] + b_dt[i];
    float r;
    if (v > 20.0f)      r = v;
    else if (v < -20.0f) r = expf(v);
    else                r = log1pf(expf(v));
    g_dt[idx] = r;
}

// ---------------- selective scan + fused gate ----------------------------
// lane-per-state; lane s==0 also applies (y + x*D) * silu(z) and stores.
__global__ __launch_bounds__(128)
void scan_kernel(const float* __restrict__ state0,
                 const float* __restrict__ A_log,
                 const float* __restrict__ Dp,
                 float* __restrict__ state_out)   // may be null
{
    int chan_base = blockIdx.x * 8;
    int ch = threadIdx.x >> 4;
    int s  = threadIdx.x & 15;
    int gchan = chan_base + ch;
    int b = gchan >> 11;
    int i = gchan & (INNER - 1);

    float a2 = -expf(A_log[(size_t)i * STATE + s]) * LOG2E;
    float Dv = Dp[i];
    float st = state0[((size_t)(b * INNER) + i) * STATE + s];

    const float* pdt = g_dt  + (size_t)(b * Ll) * INNER + i;
    const float* px  = g_xin + (size_t)(b * Ll) * INNER + i;
    const float* pB  = g_xdbl + (size_t)(b * Ll) * XDBL_N + DTRANK + s;
    const float* pC  = pB + STATE;
    const float* pz  = g_xz + (size_t)(b * Ll) * XZ_N + INNER + i;
    float*       py  = g_gate + (size_t)(b * Ll) * INNER + i;

    // software pipeline: preload t=0
    float dt = __ldg(pdt), x = __ldg(px), Bv = __ldg(pB), Cv = __ldg(pC);
    float z  = (s == 0) ? __ldg(pz) : 0.0f;

    for (int t = 0; t < Ll; t++) {
        pdt += INNER; px += INNER; pB += XDBL_N; pC += XDBL_N; pz += XZ_N;
        float ndt = 0.f, nx = 0.f, nB = 0.f, nC = 0.f, nz = 0.f;
        if (t + 1 < Ll) {
            ndt = __ldg(pdt); nx = __ldg(px);
            nB  = __ldg(pB);  nC = __ldg(pC);
            if (s == 0) nz = __ldg(pz);
        }

        float dA = ex2f(dt * a2);
        st = fmaf(dA, st, (dt * x) * Bv);
        float part = st * Cv;
        part += __shfl_xor_sync(0xffffffffu, part, 1);
        part += __shfl_xor_sync(0xffffffffu, part, 2);
        part += __shfl_xor_sync(0xffffffffu, part, 4);
        part += __shfl_xor_sync(0xffffffffu, part, 8);
        if (s == 0) {
            float sz = z / (1.0f + ex2f(-z * LOG2E));
            *py = (part + x * Dv) * sz;
        }
        py += INNER;
        dt = ndt; x = nx; Bv = nB; Cv = nC; z = nz;
    }

    if (state_out)
        state_out[((size_t)(b * INNER) + i) * STATE + s] = st;
}

// ---------------- launch ----------------
extern "C" void kernel_launch(void* const* d_in, const int* in_sizes, int n_in,
                              void* d_out, int out_size)
{
    const float* x      = (const float*)d_in[0];
    const float* state0 = (const float*)d_in[1];
    const float* W_in   = (const float*)d_in[2];
    const float* conv_w = (const float*)d_in[3];
    const float* conv_b = (const float*)d_in[4];
    const float* W_x    = (const float*)d_in[5];
    const float* W_dt   = (const float*)d_in[6];
    const float* b_dt   = (const float*)d_in[7];
    const float* A_log  = (const float*)d_in[8];
    const float* D      = (const float*)d_in[9];
    const float* W_out  = (const float*)d_in[10];

    float* out = (float*)d_out;
    const int out_main = BT * Hdim;
    const int state_elems = Bb * INNER * STATE;
    float* state_out = (out_size >= out_main + state_elems)
                         ? out + out_main : nullptr;

    float* xz   = nullptr; cudaGetSymbolAddress((void**)&xz,   g_xz);
    float* xin  = nullptr; cudaGetSymbolAddress((void**)&xin,  g_xin);
    float* xdbl = nullptr; cudaGetSymbolAddress((void**)&xdbl, g_xdbl);
    float* dtb  = nullptr; cudaGetSymbolAddress((void**)&dtb,  g_dt);
    float* gate = nullptr; cudaGetSymbolAddress((void**)&gate, g_gate);
    float* part = nullptr; cudaGetSymbolAddress((void**)&part, g_part);

    // 1) xz = x @ W_in^T : M=4096, N=4096, K=1024
    wmma_tf32_nt<<<dim3(XZ_N / 128, BT / 128, 1), 256>>>(
        x, Hdim, W_in, Hdim, xz, XZ_N, BT, XZ_N, Hdim, 1);

    // 2) depthwise conv + bias + silu -> g_xin
    {
        int n = BT * INNER;
        conv_silu_kernel<<<(n + 255) / 256, 256>>>(conv_w, conv_b);
    }

    // 3) x_dbl = xin @ W_x^T : M=4096, N=96, K=2048, split-K=8
    wmma_tf32_nt<<<dim3(1, BT / 128, NSPLIT), 256>>>(
        xin, INNER, W_x, INNER, part, XDBL_N, BT, XDBL_N, INNER, NSPLIT);
    {
        int n = BT * XDBL_N;
        splitk_reduce_kernel<<<(n + 255) / 256, 256>>>();
    }

    // 4) dt_pre = x_dbl[:, :64] @ W_dt^T : M=4096, N=2048, K=64
    wmma_tf32_nt<<<dim3(INNER / 128, BT / 128, 1), 256>>>(
        xdbl, XDBL_N, W_dt, DTRANK, dtb, INNER, BT, INNER, DTRANK, 1);

    // 5) dt = softplus(dt_pre + b_dt)
    {
        int n = BT * INNER;
        dt_softplus_kernel<<<(n + 255) / 256, 256>>>(b_dt);
    }

    // 6) selective scan with fused gating
    scan_kernel<<<(Bb * INNER) / 8, 128>>>(state0, A_log, D, state_out);

    // 7) out = gated @ W_out^T : M=4096, N=1024, K=2048
    wmma_tf32_nt<<<dim3(Hdim / 128, BT / 128, 1), 256>>>(
        gate, INNER, W_out, INNER, out, Hdim, BT, Hdim, INNER, 1);
}

// round 9
// speedup vs baseline: 1.4231x; 1.4113x over previous
#include <cuda_runtime.h>
#include <cuda_bf16.h>
#include <mma.h>
#include <math.h>
#include <cstdint>

using namespace nvcuda;

// ---------------- constants for this problem ----------------
#define Hdim   1024
#define STATE  16
#define INNER  2048           // H * 2
#define DTRANK 64             // H / 16
#define KCONV  4
#define Bb     2
#define Ll     2048
#define BT     (Bb * Ll)      // 4096 rows
#define XZ_N   (2 * INNER)    // 4096
#define XDBL_N 96             // DT_RANK + 2*STATE
#define NSPLIT 8

// ---------------- scratch (static device globals; no runtime alloc) -----
__device__ float g_xz  [(size_t)BT * XZ_N];    // xz = x @ W_in^T      (64MB)
__device__ float g_xin [(size_t)BT * INNER];   // post conv+silu       (32MB)
__device__ float g_xdbl[(size_t)BT * XDBL_N];  // x_dbl                (1.5MB)
__device__ float g_dt  [(size_t)BT * INNER];   // dt (pre then post)   (32MB)
__device__ float g_gate[(size_t)BT * INNER];   // y then gated         (32MB)
__device__ float g_part[(size_t)NSPLIT * BT * XDBL_N]; // split-K partials

// ---------------- helpers ----------------
__device__ __forceinline__ float ex2f(float x) {
    float y; asm("ex2.approx.ftz.f32 %0, %1;" : "=f"(y) : "f"(x)); return y;
}
#define LOG2E 1.4426950408889634f

__device__ __forceinline__ float to_tf32(float x) {
    float r; asm("cvt.rna.tf32.f32 %0, %1;" : "=f"(r) : "f"(x)); return r;
}
__device__ __forceinline__ float4 to_tf32_v4(float4 v) {
    v.x = to_tf32(v.x); v.y = to_tf32(v.y);
    v.z = to_tf32(v.z); v.w = to_tf32(v.w);
    return v;
}

// ---------------- tf32 WMMA NT GEMM: C[M,N] = A[M,K] * B[N,K]^T ----------
// 128x128 block tile, BK=16, 256 threads (8 warps, each 32x64 warp tile).
// tf32 rounding done ONCE at smem-store time (hot loop has no cvt).
// Optional split-K over blockIdx.z (writes partials at C + z*M*ldc).
// Requirements: M % 128 == 0, N % 16 == 0, chunk % 16 == 0.
__global__ __launch_bounds__(256, 2)
void wmma_tf32_nt(const float* __restrict__ A, int lda,
                  const float* __restrict__ B, int ldb,
                  float* __restrict__ C, int ldc,
                  int M, int N, int Ktot, int nsplit)
{
    const int BM = 128, BN = 128, BK = 16;
    const int SA = 20, SB = 20;                 // padded smem strides
    __shared__ __align__(16) float As[BM * SA];
    __shared__ __align__(16) float Bs[BN * SB];

    int tid = threadIdx.x;
    int bm  = blockIdx.y * BM;
    int bn  = blockIdx.x * BN;

    int chunk = Ktot / nsplit;
    int kFrom = blockIdx.z * chunk;
    int kTo   = kFrom + chunk;
    C += (size_t)blockIdx.z * M * ldc;          // z=0 -> no offset

    int wid = tid >> 5;
    int row0 = (wid & 3) * 32;
    int col0 = (wid >> 2) * 64;

    wmma::fragment<wmma::accumulator, 16, 16, 8, float> acc[2][4];
    #pragma unroll
    for (int i = 0; i < 2; i++)
        #pragma unroll
        for (int j = 0; j < 4; j++) wmma::fill_fragment(acc[i][j], 0.0f);

    for (int k0 = kFrom; k0 < kTo; k0 += BK) {
        // cooperative tile loads: 512 float4 per matrix, 2 per thread,
        // tf32-rounded once here (not in the MMA loop)
        #pragma unroll
        for (int it = 0; it < 2; it++) {
            int idx = tid + it * 256;           // 0..511
            int row = idx >> 2;                 // 0..127
            int kq  = (idx & 3) * 4;            // 0,4,8,12
            float4 va = make_float4(0.f, 0.f, 0.f, 0.f);
            int gr = bm + row;
            if (gr < M)
                va = *reinterpret_cast<const float4*>(&A[(size_t)gr * lda + k0 + kq]);
            *reinterpret_cast<float4*>(&As[row * SA + kq]) = to_tf32_v4(va);

            float4 vb = make_float4(0.f, 0.f, 0.f, 0.f);
            int gc = bn + row;
            if (gc < N)
                vb = *reinterpret_cast<const float4*>(&B[(size_t)gc * ldb + k0 + kq]);
            *reinterpret_cast<float4*>(&Bs[row * SB + kq]) = to_tf32_v4(vb);
        }
        __syncthreads();

        #pragma unroll
        for (int kk = 0; kk < BK; kk += 8) {
            wmma::fragment<wmma::matrix_a, 16, 16, 8, wmma::precision::tf32, wmma::row_major> a[2];
            wmma::fragment<wmma::matrix_b, 16, 16, 8, wmma::precision::tf32, wmma::col_major> b[4];
            #pragma unroll
            for (int i = 0; i < 2; i++)
                wmma::load_matrix_sync(a[i], &As[(row0 + 16 * i) * SA + kk], SA);
            #pragma unroll
            for (int j = 0; j < 4; j++)
                wmma::load_matrix_sync(b[j], &Bs[(col0 + 16 * j) * SB + kk], SB);
            #pragma unroll
            for (int i = 0; i < 2; i++)
                #pragma unroll
                for (int j = 0; j < 4; j++)
                    wmma::mma_sync(acc[i][j], a[i], b[j], acc[i][j]);
        }
        __syncthreads();
    }

    #pragma unroll
    for (int i = 0; i < 2; i++) {
        int gr0 = bm + row0 + 16 * i;
        #pragma unroll
        for (int j = 0; j < 4; j++) {
            int gc0 = bn + col0 + 16 * j;
            if (gc0 < N)
                wmma::store_matrix_sync(&C[(size_t)gr0 * ldc + gc0], acc[i][j],
                                        ldc, wmma::mem_row_major);
        }
    }
}

// ---------------- split-K reduce for x_dbl -------------------------------
__global__ void splitk_reduce_kernel()
{
    int idx = blockIdx.x * blockDim.x + threadIdx.x;
    const int n = BT * XDBL_N;
    if (idx >= n) return;
    float s = 0.0f;
    #pragma unroll
    for (int z = 0; z < NSPLIT; z++)
        s += g_part[(size_t)z * n + idx];
    g_xdbl[idx] = s;
}

// ---------------- depthwise causal conv (k=4) + bias + silu --------------
__global__ void conv_silu_kernel(const float* __restrict__ conv_w,
                                 const float* __restrict__ conv_b)
{
    int idx = blockIdx.x * blockDim.x + threadIdx.x;   // over BT*INNER
    if (idx >= BT * INNER) return;
    int i  = idx & (INNER - 1);
    int bt = idx >> 11;          // /2048
    int t  = bt & (Ll - 1);
    int b  = bt >> 11;

    float w0 = conv_w[i * KCONV + 0];
    float w1 = conv_w[i * KCONV + 1];
    float w2 = conv_w[i * KCONV + 2];
    float w3 = conv_w[i * KCONV + 3];

    const float* src = g_xz + (size_t)(b * Ll) * XZ_N + i;
    float acc = conv_b[i];
    if (t >= 3) acc = fmaf(w0, src[(size_t)(t - 3) * XZ_N], acc);
    if (t >= 2) acc = fmaf(w1, src[(size_t)(t - 2) * XZ_N], acc);
    if (t >= 1) acc = fmaf(w2, src[(size_t)(t - 1) * XZ_N], acc);
    acc = fmaf(w3, src[(size_t)t * XZ_N], acc);

    float s = 1.0f / (1.0f + ex2f(-acc * LOG2E));
    g_xin[(size_t)bt * INNER + i] = acc * s;
}

// ---------------- dt = softplus(dt_pre + b_dt) ---------------------------
__global__ void dt_softplus_kernel(const float* __restrict__ b_dt)
{
    int idx = blockIdx.x * blockDim.x + threadIdx.x;
    if (idx >= BT * INNER) return;
    int i = idx & (INNER - 1);
    float v = g_dt[idx] + b_dt[i];
    float r;
    if (v > 20.0f)      r = v;
    else if (v < -20.0f) r = expf(v);
    else                r = log1pf(expf(v));
    g_dt[idx] = r;
}

// ---------------- selective scan: lane-per-state -------------------------
// (R3-proven version: no prefetch, no fused gate — isolate GEMM change)
__global__ __launch_bounds__(128)
void scan_kernel(const float* __restrict__ state0,
                 const float* __restrict__ A_log,
                 float* __restrict__ state_out)   // may be null
{
    int chan_base = blockIdx.x * 8;
    int ch = threadIdx.x >> 4;
    int s  = threadIdx.x & 15;
    int gchan = chan_base + ch;
    int b = gchan >> 11;
    int i = gchan & (INNER - 1);

    float a2 = -expf(A_log[(size_t)i * STATE + s]) * LOG2E;
    float st = state0[((size_t)(b * INNER) + i) * STATE + s];

    const float* pdt = g_dt  + (size_t)(b * Ll) * INNER + i;
    const float* px  = g_xin + (size_t)(b * Ll) * INNER + i;
    const float* pB  = g_xdbl + (size_t)(b * Ll) * XDBL_N + DTRANK + s;
    const float* pC  = pB + STATE;
    float*       py  = g_gate + (size_t)(b * Ll) * INNER + i;

    for (int t = 0; t < Ll; t++) {
        float dt = __ldg(pdt);
        float x  = __ldg(px);
        float Bv = __ldg(pB);
        float Cv = __ldg(pC);
        float dA = ex2f(dt * a2);
        st = fmaf(dA, st, (dt * x) * Bv);
        float part = st * Cv;
        part += __shfl_xor_sync(0xffffffffu, part, 1);
        part += __shfl_xor_sync(0xffffffffu, part, 2);
        part += __shfl_xor_sync(0xffffffffu, part, 4);
        part += __shfl_xor_sync(0xffffffffu, part, 8);
        if (s == 0) *py = part;
        pdt += INNER; px += INNER; py += INNER;
        pB += XDBL_N; pC += XDBL_N;
    }

    if (state_out)
        state_out[((size_t)(b * INNER) + i) * STATE + s] = st;
}

// ---------------- gate: g = (y + xin*D) * silu(z) ------------------------
__global__ void gate_kernel(const float* __restrict__ D)
{
    int idx = blockIdx.x * blockDim.x + threadIdx.x;
    if (idx >= BT * INNER) return;
    int i  = idx & (INNER - 1);
    int bt = idx >> 11;
    float y   = g_gate[idx];
    float xin = g_xin[idx];
    float z   = g_xz[(size_t)bt * XZ_N + INNER + i];
    float sz  = z / (1.0f + ex2f(-z * LOG2E));
    g_gate[idx] = (y + xin * D[i]) * sz;
}

// ---------------- launch ----------------
extern "C" void kernel_launch(void* const* d_in, const int* in_sizes, int n_in,
                              void* d_out, int out_size)
{
    const float* x      = (const float*)d_in[0];
    const float* state0 = (const float*)d_in[1];
    const float* W_in   = (const float*)d_in[2];
    const float* conv_w = (const float*)d_in[3];
    const float* conv_b = (const float*)d_in[4];
    const float* W_x    = (const float*)d_in[5];
    const float* W_dt   = (const float*)d_in[6];
    const float* b_dt   = (const float*)d_in[7];
    const float* A_log  = (const float*)d_in[8];
    const float* D      = (const float*)d_in[9];
    const float* W_out  = (const float*)d_in[10];

    float* out = (float*)d_out;
    const int out_main = BT * Hdim;
    const int state_elems = Bb * INNER * STATE;
    float* state_out = (out_size >= out_main + state_elems)
                         ? out + out_main : nullptr;

    float* xz   = nullptr; cudaGetSymbolAddress((void**)&xz,   g_xz);
    float* xin  = nullptr; cudaGetSymbolAddress((void**)&xin,  g_xin);
    float* xdbl = nullptr; cudaGetSymbolAddress((void**)&xdbl, g_xdbl);
    float* dtb  = nullptr; cudaGetSymbolAddress((void**)&dtb,  g_dt);
    float* gate = nullptr; cudaGetSymbolAddress((void**)&gate, g_gate);
    float* part = nullptr; cudaGetSymbolAddress((void**)&part, g_part);

    // 1) xz = x @ W_in^T : M=4096, N=4096, K=1024
    wmma_tf32_nt<<<dim3(XZ_N / 128, BT / 128, 1), 256>>>(
        x, Hdim, W_in, Hdim, xz, XZ_N, BT, XZ_N, Hdim, 1);

    // 2) depthwise conv + bias + silu -> g_xin
    {
        int n = BT * INNER;
        conv_silu_kernel<<<(n + 255) / 256, 256>>>(conv_w, conv_b);
    }

    // 3) x_dbl = xin @ W_x^T : M=4096, N=96, K=2048, split-K=8
    wmma_tf32_nt<<<dim3(1, BT / 128, NSPLIT), 256>>>(
        xin, INNER, W_x, INNER, part, XDBL_N, BT, XDBL_N, INNER, NSPLIT);
    {
        int n = BT * XDBL_N;
        splitk_reduce_kernel<<<(n + 255) / 256, 256>>>();
    }

    // 4) dt_pre = x_dbl[:, :64] @ W_dt^T : M=4096, N=2048, K=64
    wmma_tf32_nt<<<dim3(INNER / 128, BT / 128, 1), 256>>>(
        xdbl, XDBL_N, W_dt, DTRANK, dtb, INNER, BT, INNER, DTRANK, 1);

    // 5) dt = softplus(dt_pre + b_dt)
    {
        int n = BT * INNER;
        dt_softplus_kernel<<<(n + 255) / 256, 256>>>(b_dt);
    }

    // 6) selective scan
    scan_kernel<<<(Bb * INNER) / 8, 128>>>(state0, A_log, state_out);

    // 7) gating
    {
        int n = BT * INNER;
        gate_kernel<<<(n + 255) / 256, 256>>>(D);
    }

    // 8) out = gated @ W_out^T : M=4096, N=1024, K=2048
    wmma_tf32_nt<<<dim3(Hdim / 128, BT / 128, 1), 256>>>(
        gate, INNER, W_out, INNER, out, Hdim, BT, Hdim, INNER, 1);
}